// round 1
// baseline (speedup 1.0000x reference)
#include <cuda_runtime.h>
#include <math_constants.h>
#include <cstdint>

#define Bb 2048
#define Tt 200
#define Hh 256
#define Kk 8

// Scratch (no allocations allowed): transposed Wk, r = Wk@q per batch, cb = bk.q per batch
__device__ float g_WkT[Hh * Hh];
__device__ float g_R[Bb * Hh];
__device__ float g_cb[Bb];

// ---------------------------------------------------------------------------
// Kernel 1: transpose Wk so the r-projection reads coalesced columns.
// WkT[j*H + o] = Wk[o*H + j]
// ---------------------------------------------------------------------------
__global__ void transpose_wk(const float* __restrict__ Wk) {
    int n = blockIdx.x * 256 + threadIdx.x;   // n < H*H = 65536
    int j = n >> 8;
    int o = n & 255;
    g_WkT[n] = Wk[o * Hh + j];
}

// ---------------------------------------------------------------------------
// Kernel 2: per 16 batches: q = cs@Wq + bq (kept in smem), r = Wk@q, cb = bk.q
// Thread j owns output column j; 16 accumulators amortize each weight load.
// ---------------------------------------------------------------------------
__global__ void __launch_bounds__(256) proj_kernel(
    const float* __restrict__ cs, const float* __restrict__ Wq,
    const float* __restrict__ bq, const float* __restrict__ bk) {
    __shared__ float cs_s[16][Hh];
    __shared__ float q_s[16][Hh];
    const int j = threadIdx.x;
    const int b0 = blockIdx.x * 16;

    #pragma unroll
    for (int m = 0; m < 16; m++) cs_s[m][j] = cs[(size_t)(b0 + m) * Hh + j];
    __syncthreads();

    float acc[16];
    const float bqj = bq[j];
    #pragma unroll
    for (int m = 0; m < 16; m++) acc[m] = bqj;
    for (int i = 0; i < Hh; i++) {
        float w = Wq[i * Hh + j];
        #pragma unroll
        for (int m = 0; m < 16; m++) acc[m] += cs_s[m][i] * w;
    }
    #pragma unroll
    for (int m = 0; m < 16; m++) q_s[m][j] = acc[m];
    __syncthreads();

    // r[b, o=j] = sum_i WkT[i*H + o] * q[b, i]
    #pragma unroll
    for (int m = 0; m < 16; m++) acc[m] = 0.f;
    for (int i = 0; i < Hh; i++) {
        float w = g_WkT[i * Hh + j];
        #pragma unroll
        for (int m = 0; m < 16; m++) acc[m] += q_s[m][i] * w;
    }
    #pragma unroll
    for (int m = 0; m < 16; m++) g_R[(size_t)(b0 + m) * Hh + j] = acc[m];

    if (j < 16) {
        float s = 0.f;
        for (int i = 0; i < Hh; i++) s += bk[i] * q_s[j][i];
        g_cb[b0 + j] = s;
    }
}

// ---------------------------------------------------------------------------
// Kernel 3: per-batch fused scores -> softmax -> top-8 -> attn/selected out ->
// sparse V projection -> summary.
// ---------------------------------------------------------------------------
__global__ void __launch_bounds__(256) main_kernel(
    const float* __restrict__ ss, const unsigned int* __restrict__ mask,
    const float* __restrict__ Wv, const float* __restrict__ bv,
    float* __restrict__ out) {
    __shared__ float r_s[Hh];
    __shared__ float sc_s[Tt];          // scores, later reused for final attn
    __shared__ float ssel[Kk][Hh];      // gathered selected state rows
    __shared__ float redf[8];
    __shared__ int   redi[8];
    __shared__ float selval[Kk];
    __shared__ int   selidx[Kk];
    __shared__ float f_bcast;
    __shared__ int   i_bcast;

    const int tid  = threadIdx.x;
    const int lane = tid & 31;
    const int wid  = tid >> 5;
    const int b    = blockIdx.x;
    const float* ssb = ss + (size_t)b * Tt * Hh;

    r_s[tid] = g_R[(size_t)b * Hh + tid];
    const float cb = g_cb[b];

    // valid count (mask read works for int32 {0,1} and float32 {0.0,1.0})
    int mt = 0;
    if (tid < Tt) mt = (mask[(size_t)b * Tt + tid] != 0u) ? 1 : 0;
    int sv = mt;
    #pragma unroll
    for (int o = 16; o; o >>= 1) sv += __shfl_xor_sync(0xffffffffu, sv, o);
    if (lane == 0) redi[wid] = sv;
    __syncthreads();
    if (wid == 0) {
        int v = (lane < 8) ? redi[lane] : 0;
        #pragma unroll
        for (int o = 4; o; o >>= 1) v += __shfl_xor_sync(0xffffffffu, v, o);
        if (lane == 0) i_bcast = v;
    }
    __syncthreads();
    const int lim = i_bcast - 1;
    const bool hist = (tid < Tt) && mt && (tid < lim);

    // scores: warp per t, lane owns 8 contiguous elements (two float4 loads)
    float rr[8];
    #pragma unroll
    for (int e = 0; e < 8; e++) rr[e] = r_s[lane * 8 + e];
    for (int t = wid; t < Tt; t += 8) {
        const float4* row = (const float4*)(ssb + (size_t)t * Hh);
        float4 a = row[lane * 2];
        float4 c = row[lane * 2 + 1];
        float d = a.x * rr[0] + a.y * rr[1] + a.z * rr[2] + a.w * rr[3]
                + c.x * rr[4] + c.y * rr[5] + c.z * rr[6] + c.w * rr[7];
        #pragma unroll
        for (int o = 16; o; o >>= 1) d += __shfl_xor_sync(0xffffffffu, d, o);
        if (lane == 0) sc_s[t] = (d + cb) * 0.0625f;   // /sqrt(256)
    }
    __syncthreads();

    // softmax (only ratios of kept values matter downstream)
    float sc = hist ? sc_s[tid] : -CUDART_INF_F;
    float mv = sc;
    #pragma unroll
    for (int o = 16; o; o >>= 1) mv = fmaxf(mv, __shfl_xor_sync(0xffffffffu, mv, o));
    if (lane == 0) redf[wid] = mv;
    __syncthreads();
    if (wid == 0) {
        float v = (lane < 8) ? redf[lane] : -CUDART_INF_F;
        #pragma unroll
        for (int o = 4; o; o >>= 1) v = fmaxf(v, __shfl_xor_sync(0xffffffffu, v, o));
        if (lane == 0) f_bcast = v;
    }
    __syncthreads();
    const float mx = f_bcast;
    const float p = hist ? __expf(sc - mx) : 0.f;
    float selv = (tid < Tt) ? (hist ? p : -1.f) : -2.f;

    // top-8 via repeated block argmax (val desc, tie -> lowest index)
    for (int k = 0; k < Kk; k++) {
        float v = selv; int ix = tid;
        #pragma unroll
        for (int o = 16; o; o >>= 1) {
            float vo = __shfl_xor_sync(0xffffffffu, v, o);
            int   io = __shfl_xor_sync(0xffffffffu, ix, o);
            if (vo > v || (vo == v && io < ix)) { v = vo; ix = io; }
        }
        if (lane == 0) { redf[wid] = v; redi[wid] = ix; }
        __syncthreads();
        if (wid == 0) {
            float v2 = (lane < 8) ? redf[lane] : -3.f;
            int   i2 = (lane < 8) ? redi[lane] : 0x7fffffff;
            #pragma unroll
            for (int o = 4; o; o >>= 1) {
                float vo = __shfl_xor_sync(0xffffffffu, v2, o);
                int   io = __shfl_xor_sync(0xffffffffu, i2, o);
                if (vo > v2 || (vo == v2 && io < i2)) { v2 = vo; i2 = io; }
            }
            if (lane == 0) { selval[k] = v2; selidx[k] = i2; }
        }
        __syncthreads();
        if (tid == selidx[k]) selv = -2.f;
    }

    float s8 = 0.f;
    #pragma unroll
    for (int k = 0; k < Kk; k++) s8 += fmaxf(selval[k], 0.f);
    s8 = fmaxf(s8, 1.1920929e-07f);

    // attn output (sparse, renormalized) + selected indices
    if (tid < Tt) sc_s[tid] = 0.f;
    __syncthreads();
    if (tid < Kk && selval[tid] > 0.f) sc_s[selidx[tid]] = selval[tid] / s8;
    __syncthreads();
    if (tid < Tt)
        out[(size_t)Bb * Hh + (size_t)b * Tt + tid] = sc_s[tid];
    if (tid < Kk)
        out[(size_t)Bb * Hh + (size_t)Bb * Tt + (size_t)b * Kk + tid] =
            (selval[tid] > 0.f) ? (float)selidx[tid] : -1.0f;

    // gather selected rows
    for (int e = tid; e < Kk * Hh; e += 256) {
        int k = e >> 8, i = e & 255;
        float val = 0.f;
        if (selval[k] > 0.f) {
            int t = selidx[k];                 // < Tt guaranteed when selval > 0
            val = ssb[(size_t)t * Hh + i];
        }
        ssel[k][i] = val;
    }
    __syncthreads();

    // sparse V projection: thread = output column h; 8 accumulators reuse each Wv load
    float acc[Kk];
    #pragma unroll
    for (int k = 0; k < Kk; k++) acc[k] = 0.f;
    const float* wv = Wv + tid;
    #pragma unroll 4
    for (int i = 0; i < Hh; i++) {
        float w = wv[(size_t)i * Hh];
        #pragma unroll
        for (int k = 0; k < Kk; k++) acc[k] += ssel[k][i] * w;
    }
    const float bvh = bv[tid];
    float sum = 0.f;
    #pragma unroll
    for (int k = 0; k < Kk; k++) {
        float wgt = (selval[k] > 0.f) ? (selval[k] / s8) : 0.f;
        sum += wgt * fmaxf(acc[k] + bvh, 0.f);
    }
    out[(size_t)b * Hh + tid] = sum;
}

// ---------------------------------------------------------------------------
extern "C" void kernel_launch(void* const* d_in, const int* in_sizes, int n_in,
                              void* d_out, int out_size) {
    const float* cs = (const float*)d_in[0];          // current_state (B,H)
    const float* ss = (const float*)d_in[1];          // state_sequence (B,T,H)
    const unsigned int* mask = (const unsigned int*)d_in[2]; // visit_mask (B,T)
    const float* Wq = (const float*)d_in[3];
    const float* bq = (const float*)d_in[4];
    const float* Wk = (const float*)d_in[5];
    const float* bk = (const float*)d_in[6];
    const float* Wv = (const float*)d_in[7];
    const float* bv = (const float*)d_in[8];
    float* out = (float*)d_out;

    transpose_wk<<<(Hh * Hh) / 256, 256>>>(Wk);
    proj_kernel<<<Bb / 16, 256>>>(cs, Wq, bq, bk);
    main_kernel<<<Bb, 256>>>(ss, mask, Wv, bv, out);
}

// round 2
// speedup vs baseline: 1.0303x; 1.0303x over previous
#include <cuda_runtime.h>
#include <math_constants.h>
#include <cstdint>

#define Bb 2048
#define Tt 200
#define Hh 256
#define Kk 8
#define Gg 4

typedef unsigned long long ull;

// scratch (no allocs allowed)
__device__ float g_WkT[Hh * Hh];
__device__ float g_R[Bb * Hh];
__device__ float g_cb[Bb];
__device__ int   g_selidx[Bb * Kk];
__device__ float g_selw[Bb * Kk];

// ---- packed f32x2 helpers (Blackwell FFMA2 path, PTX-only) ----
__device__ __forceinline__ ull pk2(float x, float y) {
    ull r; asm("mov.b64 %0,{%1,%2};" : "=l"(r) : "f"(x), "f"(y)); return r;
}
__device__ __forceinline__ void upk2(ull v, float& x, float& y) {
    asm("mov.b64 {%0,%1},%2;" : "=f"(x), "=f"(y) : "l"(v));
}
__device__ __forceinline__ void fma2(ull& d, ull a, ull b) {
    asm("fma.rn.f32x2 %0,%1,%2,%0;" : "+l"(d) : "l"(a), "l"(b));
}

// ---------------------------------------------------------------------------
// Kernel 1: coalesced smem-tile transpose of Wk.
// ---------------------------------------------------------------------------
__global__ void __launch_bounds__(256) transpose_wk(const float* __restrict__ Wk) {
    __shared__ float tile[32][33];
    int x = blockIdx.x * 32 + threadIdx.x;
    int y = blockIdx.y * 32 + threadIdx.y;
    #pragma unroll
    for (int j = 0; j < 32; j += 8)
        tile[threadIdx.y + j][threadIdx.x] = Wk[(size_t)(y + j) * Hh + x];
    __syncthreads();
    int xo = blockIdx.y * 32 + threadIdx.x;
    int yo = blockIdx.x * 32 + threadIdx.y;
    #pragma unroll
    for (int j = 0; j < 32; j += 8)
        g_WkT[(size_t)(yo + j) * Hh + xo] = tile[threadIdx.x][threadIdx.y + j];
}

// ---------------------------------------------------------------------------
// Kernel 2: per 16 batches: q = cs@Wq + bq, r = Wk@q, cb = bk.q
// Batch-interleaved smem layout so FFMA2 packs batch pairs.
// ---------------------------------------------------------------------------
__global__ void __launch_bounds__(256) proj_kernel(
    const float* __restrict__ cs, const float* __restrict__ Wq,
    const float* __restrict__ bq, const float* __restrict__ bk) {
    __shared__ float cs_s[Hh][20];   // [i][m], padded to 20 for 16B alignment
    __shared__ float q_s[Hh][20];
    const int j  = threadIdx.x;
    const int b0 = blockIdx.x * 16;

    #pragma unroll
    for (int m = 0; m < 16; m++) cs_s[j][m] = cs[(size_t)(b0 + m) * Hh + j];
    __syncthreads();

    ull acc[8];
    const float bqj = bq[j];
    const ull binit = pk2(bqj, bqj);
    #pragma unroll
    for (int q = 0; q < 8; q++) acc[q] = binit;
    #pragma unroll 4
    for (int i = 0; i < Hh; i++) {
        float w = Wq[(size_t)i * Hh + j];
        ull ww = pk2(w, w);
        #pragma unroll
        for (int p = 0; p < 4; p++) {
            ulonglong2 A = *(const ulonglong2*)&cs_s[i][4 * p];
            fma2(acc[2 * p], A.x, ww);
            fma2(acc[2 * p + 1], A.y, ww);
        }
    }
    #pragma unroll
    for (int q = 0; q < 8; q++) upk2(acc[q], q_s[j][2 * q], q_s[j][2 * q + 1]);
    __syncthreads();

    #pragma unroll
    for (int q = 0; q < 8; q++) acc[q] = pk2(0.f, 0.f);
    #pragma unroll 4
    for (int i = 0; i < Hh; i++) {
        float w = g_WkT[(size_t)i * Hh + j];
        ull ww = pk2(w, w);
        #pragma unroll
        for (int p = 0; p < 4; p++) {
            ulonglong2 A = *(const ulonglong2*)&q_s[i][4 * p];
            fma2(acc[2 * p], A.x, ww);
            fma2(acc[2 * p + 1], A.y, ww);
        }
    }
    #pragma unroll
    for (int q = 0; q < 8; q++) {
        float a, b;
        upk2(acc[q], a, b);
        g_R[(size_t)(b0 + 2 * q) * Hh + j]     = a;
        g_R[(size_t)(b0 + 2 * q + 1) * Hh + j] = b;
    }
    if (j < 16) {
        float s = 0.f;
        for (int i = 0; i < Hh; i++) s += bk[i] * q_s[i][j];
        g_cb[b0 + j] = s;
    }
}

// ---------------------------------------------------------------------------
// Kernel 3: scores -> top-8 (on raw scores, exp only on winners) ->
// attn + selected outputs + selidx/selw scratch.
// ---------------------------------------------------------------------------
__global__ void __launch_bounds__(256) score_kernel(
    const float* __restrict__ ss, const unsigned int* __restrict__ mask,
    float* __restrict__ out) {
    __shared__ float r_s[Hh];
    __shared__ float sraw[Tt];
    __shared__ float msc[256];
    __shared__ int   redi[8];
    __shared__ int   i_bcast;

    const int tid  = threadIdx.x;
    const int lane = tid & 31;
    const int wid  = tid >> 5;
    const int b    = blockIdx.x;
    const float* ssb = ss + (size_t)b * Tt * Hh;

    r_s[tid] = g_R[(size_t)b * Hh + tid];
    const float cb = g_cb[b];

    int mt = 0;
    if (tid < Tt) mt = (mask[(size_t)b * Tt + tid] != 0u) ? 1 : 0;
    int sv = mt;
    #pragma unroll
    for (int o = 16; o; o >>= 1) sv += __shfl_xor_sync(0xffffffffu, sv, o);
    if (lane == 0) redi[wid] = sv;
    __syncthreads();
    if (wid == 0) {
        int v = (lane < 8) ? redi[lane] : 0;
        #pragma unroll
        for (int o = 4; o; o >>= 1) v += __shfl_xor_sync(0xffffffffu, v, o);
        if (lane == 0) i_bcast = v;
    }
    // zero the attn output row while waiting
    if (tid < Tt) out[(size_t)Bb * Hh + (size_t)b * Tt + tid] = 0.f;
    __syncthreads();
    const int lim = i_bcast - 1;
    const bool hist = (tid < Tt) && mt && (tid < lim);

    float rr[8];
    #pragma unroll
    for (int e = 0; e < 8; e++) rr[e] = r_s[lane * 8 + e];

    // 12 paired iterations (6 shuffles / 2 rows) + 1 leftover row
    #pragma unroll 2
    for (int m = 0; m < 12; m++) {
        int t0 = wid + 16 * m;
        int t1 = t0 + 8;
        const float4* r0 = (const float4*)(ssb + (size_t)t0 * Hh);
        const float4* r1 = (const float4*)(ssb + (size_t)t1 * Hh);
        float4 a0 = r0[lane * 2], c0 = r0[lane * 2 + 1];
        float4 a1 = r1[lane * 2], c1 = r1[lane * 2 + 1];
        float d0 = a0.x * rr[0] + a0.y * rr[1] + a0.z * rr[2] + a0.w * rr[3]
                 + c0.x * rr[4] + c0.y * rr[5] + c0.z * rr[6] + c0.w * rr[7];
        float d1 = a1.x * rr[0] + a1.y * rr[1] + a1.z * rr[2] + a1.w * rr[3]
                 + c1.x * rr[4] + c1.y * rr[5] + c1.z * rr[6] + c1.w * rr[7];
        d0 += __shfl_xor_sync(0xffffffffu, d0, 16);
        d1 += __shfl_xor_sync(0xffffffffu, d1, 16);
        float e = (lane < 16) ? d0 : d1;
        e += __shfl_xor_sync(0xffffffffu, e, 8);
        e += __shfl_xor_sync(0xffffffffu, e, 4);
        e += __shfl_xor_sync(0xffffffffu, e, 2);
        e += __shfl_xor_sync(0xffffffffu, e, 1);
        if (lane == 0)  sraw[t0] = (e + cb) * 0.0625f;
        if (lane == 16) sraw[t1] = (e + cb) * 0.0625f;
    }
    {
        int t = 192 + wid;   // 192..199
        const float4* r0 = (const float4*)(ssb + (size_t)t * Hh);
        float4 a = r0[lane * 2], c = r0[lane * 2 + 1];
        float d = a.x * rr[0] + a.y * rr[1] + a.z * rr[2] + a.w * rr[3]
                + c.x * rr[4] + c.y * rr[5] + c.z * rr[6] + c.w * rr[7];
        #pragma unroll
        for (int o = 16; o; o >>= 1) d += __shfl_xor_sync(0xffffffffu, d, o);
        if (lane == 0) sraw[t] = (d + cb) * 0.0625f;
    }
    __syncthreads();
    msc[tid] = ((tid < Tt) && hist) ? sraw[tid] : -CUDART_INF_F;
    __syncthreads();

    if (wid == 0) {
        float v[7];
        #pragma unroll
        for (int j = 0; j < 7; j++) v[j] = msc[lane + 32 * j];   // covers 0..223

        float kval[8]; int kidx[8];
        #pragma unroll
        for (int k = 0; k < Kk; k++) {
            float bv_ = -CUDART_INF_F; int bi = 0x7fffffff;
            #pragma unroll
            for (int j = 0; j < 7; j++) {
                int ix = lane + 32 * j;
                if (v[j] > bv_ || (v[j] == bv_ && ix < bi)) { bv_ = v[j]; bi = ix; }
            }
            float wv_ = bv_; int wi = bi;
            #pragma unroll
            for (int o = 16; o; o >>= 1) {
                float ov = __shfl_xor_sync(0xffffffffu, wv_, o);
                int   oi = __shfl_xor_sync(0xffffffffu, wi, o);
                if (ov > wv_ || (ov == wv_ && oi < wi)) { wv_ = ov; wi = oi; }
            }
            kval[k] = wv_; kidx[k] = wi;
            #pragma unroll
            for (int j = 0; j < 7; j++)
                if (wi == lane + 32 * j) v[j] = -CUDART_INF_F;
        }

        const float kmax = kval[0];
        float p[8]; float sum = 0.f;
        #pragma unroll
        for (int k = 0; k < Kk; k++) {
            bool val = kval[k] > -1e30f;
            p[k] = val ? __expf(kval[k] - kmax) : 0.f;
            sum += p[k];
        }
        const float inv = 1.f / fmaxf(sum, 1.1920929e-07f);

        float myv = kval[0], myp = p[0]; int myi = kidx[0];
        #pragma unroll
        for (int k = 1; k < Kk; k++)
            if (lane == k) { myv = kval[k]; myp = p[k]; myi = kidx[k]; }

        if (lane < Kk) {
            bool val = myv > -1e30f;
            float w = val ? myp * inv : 0.f;
            g_selidx[b * Kk + lane] = val ? myi : -1;
            g_selw[b * Kk + lane]   = w;
            out[(size_t)Bb * Hh + (size_t)Bb * Tt + (size_t)b * Kk + lane] =
                val ? (float)myi : -1.f;
            if (val) out[(size_t)Bb * Hh + (size_t)b * Tt + myi] = w;
        }
    }
}

// ---------------------------------------------------------------------------
// Kernel 4: sparse V projection over 4 batches x 8 selected rows per block,
// packed FFMA2, Wv load amortized over 32 FMAs.
// ---------------------------------------------------------------------------
__global__ void __launch_bounds__(256) v_kernel(
    const float* __restrict__ ss, const float* __restrict__ Wv,
    const float* __restrict__ bv, float* __restrict__ out) {
    __shared__ float ssel[Hh][Gg * Kk + 4];   // [256][36], 16B-aligned groups
    __shared__ int   sidx[Gg * Kk];
    __shared__ float swt[Gg * Kk];

    const int tid = threadIdx.x;
    const int b0  = blockIdx.x * Gg;

    if (tid < Gg * Kk) {
        sidx[tid] = g_selidx[b0 * Kk + tid];
        swt[tid]  = g_selw[b0 * Kk + tid];
    }
    __syncthreads();

    #pragma unroll 4
    for (int r = 0; r < Gg * Kk; r++) {
        int t = sidx[r];
        int g = r >> 3;
        float val = 0.f;
        if (t >= 0) val = ss[((size_t)(b0 + g) * Tt + t) * Hh + tid];
        ssel[tid][r] = val;
    }
    __syncthreads();

    ull acc[16];
    #pragma unroll
    for (int q = 0; q < 16; q++) acc[q] = pk2(0.f, 0.f);

    const float* wp = Wv + tid;
    #pragma unroll 2
    for (int i = 0; i < Hh; i++) {
        float w = __ldg(wp + (size_t)i * Hh);
        ull ww = pk2(w, w);
        #pragma unroll
        for (int g = 0; g < Gg; g++) {
            ulonglong2 A = *(const ulonglong2*)&ssel[i][g * 8];
            ulonglong2 B = *(const ulonglong2*)&ssel[i][g * 8 + 4];
            fma2(acc[g * 4 + 0], A.x, ww);
            fma2(acc[g * 4 + 1], A.y, ww);
            fma2(acc[g * 4 + 2], B.x, ww);
            fma2(acc[g * 4 + 3], B.y, ww);
        }
    }

    const float bvh = bv[tid];
    #pragma unroll
    for (int g = 0; g < Gg; g++) {
        float s = 0.f;
        #pragma unroll
        for (int j = 0; j < 4; j++) {
            float a, c;
            upk2(acc[g * 4 + j], a, c);
            s += swt[g * 8 + 2 * j]     * fmaxf(a + bvh, 0.f);
            s += swt[g * 8 + 2 * j + 1] * fmaxf(c + bvh, 0.f);
        }
        out[(size_t)(b0 + g) * Hh + tid] = s;
    }
}

// ---------------------------------------------------------------------------
extern "C" void kernel_launch(void* const* d_in, const int* in_sizes, int n_in,
                              void* d_out, int out_size) {
    const float* cs = (const float*)d_in[0];
    const float* ss = (const float*)d_in[1];
    const unsigned int* mask = (const unsigned int*)d_in[2];
    const float* Wq = (const float*)d_in[3];
    const float* bq = (const float*)d_in[4];
    const float* Wk = (const float*)d_in[5];
    const float* bk = (const float*)d_in[6];
    const float* Wv = (const float*)d_in[7];
    const float* bv = (const float*)d_in[8];
    float* out = (float*)d_out;

    dim3 tb(32, 8);
    dim3 tg(8, 8);
    transpose_wk<<<tg, tb>>>(Wk);
    proj_kernel<<<Bb / 16, 256>>>(cs, Wq, bq, bk);
    score_kernel<<<Bb, 256>>>(ss, mask, out);
    v_kernel<<<Bb / Gg, 256>>>(ss, Wv, bv, out);
}

// round 3
// speedup vs baseline: 1.5413x; 1.4960x over previous
#include <cuda_runtime.h>
#include <math_constants.h>
#include <cstdint>

#define Bb 2048
#define Tt 200
#define Hh 256
#define Kk 8
#define Gg 4

typedef unsigned long long ull;

// scratch (no allocs allowed)
__device__ float g_WkT[Hh * Hh];
__device__ float g_R[Bb * Hh];
__device__ float g_cb[Bb];
__device__ int   g_selidx[Bb * Kk];
__device__ float g_selw[Bb * Kk];

// ---- packed f32x2 helpers (Blackwell FFMA2 path, PTX-only) ----
__device__ __forceinline__ ull pk2(float x, float y) {
    ull r; asm("mov.b64 %0,{%1,%2};" : "=l"(r) : "f"(x), "f"(y)); return r;
}
__device__ __forceinline__ void upk2(ull v, float& x, float& y) {
    asm("mov.b64 {%0,%1},%2;" : "=f"(x), "=f"(y) : "l"(v));
}
__device__ __forceinline__ void fma2(ull& d, ull a, ull b) {
    asm("fma.rn.f32x2 %0,%1,%2,%0;" : "+l"(d) : "l"(a), "l"(b));
}

// ---------------------------------------------------------------------------
// Kernel 1: coalesced smem-tile transpose of Wk.
// ---------------------------------------------------------------------------
__global__ void __launch_bounds__(256) transpose_wk(const float* __restrict__ Wk) {
    __shared__ float tile[32][33];
    int x = blockIdx.x * 32 + threadIdx.x;
    int y = blockIdx.y * 32 + threadIdx.y;
    #pragma unroll
    for (int j = 0; j < 32; j += 8)
        tile[threadIdx.y + j][threadIdx.x] = Wk[(size_t)(y + j) * Hh + x];
    __syncthreads();
    int xo = blockIdx.y * 32 + threadIdx.x;
    int yo = blockIdx.x * 32 + threadIdx.y;
    #pragma unroll
    for (int j = 0; j < 32; j += 8)
        g_WkT[(size_t)(yo + j) * Hh + xo] = tile[threadIdx.x][threadIdx.y + j];
}

// ---------------------------------------------------------------------------
// Kernel 2: 8 batches/block (256 blocks): q = cs@Wq + bq, r = Wk@q, cb = bk.q
// ---------------------------------------------------------------------------
__global__ void __launch_bounds__(256) proj_kernel(
    const float* __restrict__ cs, const float* __restrict__ Wq,
    const float* __restrict__ bq, const float* __restrict__ bk) {
    __shared__ float cs_s[Hh][8];
    __shared__ float q_s[Hh][8];
    const int j  = threadIdx.x;
    const int b0 = blockIdx.x * 8;

    #pragma unroll
    for (int m = 0; m < 8; m++) cs_s[j][m] = cs[(size_t)(b0 + m) * Hh + j];
    __syncthreads();

    ull acc[4];
    const float bqj = bq[j];
    const ull binit = pk2(bqj, bqj);
    #pragma unroll
    for (int q = 0; q < 4; q++) acc[q] = binit;
    #pragma unroll 8
    for (int i = 0; i < Hh; i++) {
        float w = Wq[(size_t)i * Hh + j];
        ull ww = pk2(w, w);
        ulonglong2 A = *(const ulonglong2*)&cs_s[i][0];
        ulonglong2 B = *(const ulonglong2*)&cs_s[i][4];
        fma2(acc[0], A.x, ww); fma2(acc[1], A.y, ww);
        fma2(acc[2], B.x, ww); fma2(acc[3], B.y, ww);
    }
    #pragma unroll
    for (int q = 0; q < 4; q++) upk2(acc[q], q_s[j][2 * q], q_s[j][2 * q + 1]);
    __syncthreads();

    #pragma unroll
    for (int q = 0; q < 4; q++) acc[q] = pk2(0.f, 0.f);
    #pragma unroll 8
    for (int i = 0; i < Hh; i++) {
        float w = g_WkT[(size_t)i * Hh + j];
        ull ww = pk2(w, w);
        ulonglong2 A = *(const ulonglong2*)&q_s[i][0];
        ulonglong2 B = *(const ulonglong2*)&q_s[i][4];
        fma2(acc[0], A.x, ww); fma2(acc[1], A.y, ww);
        fma2(acc[2], B.x, ww); fma2(acc[3], B.y, ww);
    }
    #pragma unroll
    for (int q = 0; q < 4; q++) {
        float a, b;
        upk2(acc[q], a, b);
        g_R[(size_t)(b0 + 2 * q) * Hh + j]     = a;
        g_R[(size_t)(b0 + 2 * q + 1) * Hh + j] = b;
    }
    if (j < 8) {
        float s = 0.f;
        for (int i = 0; i < Hh; i++) s += bk[i] * q_s[i][j];
        g_cb[b0 + j] = s;
    }
}

// ---------------------------------------------------------------------------
// Kernel 3: scores -> top-8 on raw scores -> attn + selected + scratch.
// ---------------------------------------------------------------------------
__global__ void __launch_bounds__(256) score_kernel(
    const float* __restrict__ ss, const unsigned int* __restrict__ mask,
    float* __restrict__ out) {
    __shared__ float r_s[Hh];
    __shared__ float sraw[Tt];
    __shared__ float msc[256];
    __shared__ int   redi[8];
    __shared__ int   i_bcast;

    const int tid  = threadIdx.x;
    const int lane = tid & 31;
    const int wid  = tid >> 5;
    const int b    = blockIdx.x;
    const float* ssb = ss + (size_t)b * Tt * Hh;

    r_s[tid] = g_R[(size_t)b * Hh + tid];
    const float cb = g_cb[b];

    int mt = 0;
    if (tid < Tt) mt = (mask[(size_t)b * Tt + tid] != 0u) ? 1 : 0;
    int sv = mt;
    #pragma unroll
    for (int o = 16; o; o >>= 1) sv += __shfl_xor_sync(0xffffffffu, sv, o);
    if (lane == 0) redi[wid] = sv;
    __syncthreads();
    if (wid == 0) {
        int v = (lane < 8) ? redi[lane] : 0;
        #pragma unroll
        for (int o = 4; o; o >>= 1) v += __shfl_xor_sync(0xffffffffu, v, o);
        if (lane == 0) i_bcast = v;
    }
    if (tid < Tt) out[(size_t)Bb * Hh + (size_t)b * Tt + tid] = 0.f;
    __syncthreads();
    const int lim = i_bcast - 1;
    const bool hist = (tid < Tt) && mt && (tid < lim);

    float rr[8];
    #pragma unroll
    for (int e = 0; e < 8; e++) rr[e] = r_s[lane * 8 + e];

    // 12 paired iterations (6 shuffles / 2 rows) + 1 leftover row
    #pragma unroll 3
    for (int m = 0; m < 12; m++) {
        int t0 = wid + 16 * m;
        int t1 = t0 + 8;
        const float4* r0 = (const float4*)(ssb + (size_t)t0 * Hh);
        const float4* r1 = (const float4*)(ssb + (size_t)t1 * Hh);
        float4 a0 = __ldcs(r0 + lane * 2), c0 = __ldcs(r0 + lane * 2 + 1);
        float4 a1 = __ldcs(r1 + lane * 2), c1 = __ldcs(r1 + lane * 2 + 1);
        float d0 = a0.x * rr[0] + a0.y * rr[1] + a0.z * rr[2] + a0.w * rr[3]
                 + c0.x * rr[4] + c0.y * rr[5] + c0.z * rr[6] + c0.w * rr[7];
        float d1 = a1.x * rr[0] + a1.y * rr[1] + a1.z * rr[2] + a1.w * rr[3]
                 + c1.x * rr[4] + c1.y * rr[5] + c1.z * rr[6] + c1.w * rr[7];
        d0 += __shfl_xor_sync(0xffffffffu, d0, 16);
        d1 += __shfl_xor_sync(0xffffffffu, d1, 16);
        float e = (lane < 16) ? d0 : d1;
        e += __shfl_xor_sync(0xffffffffu, e, 8);
        e += __shfl_xor_sync(0xffffffffu, e, 4);
        e += __shfl_xor_sync(0xffffffffu, e, 2);
        e += __shfl_xor_sync(0xffffffffu, e, 1);
        if (lane == 0)  sraw[t0] = (e + cb) * 0.0625f;
        if (lane == 16) sraw[t1] = (e + cb) * 0.0625f;
    }
    {
        int t = 192 + wid;
        const float4* r0 = (const float4*)(ssb + (size_t)t * Hh);
        float4 a = __ldcs(r0 + lane * 2), c = __ldcs(r0 + lane * 2 + 1);
        float d = a.x * rr[0] + a.y * rr[1] + a.z * rr[2] + a.w * rr[3]
                + c.x * rr[4] + c.y * rr[5] + c.z * rr[6] + c.w * rr[7];
        #pragma unroll
        for (int o = 16; o; o >>= 1) d += __shfl_xor_sync(0xffffffffu, d, o);
        if (lane == 0) sraw[t] = (d + cb) * 0.0625f;
    }
    __syncthreads();
    msc[tid] = ((tid < Tt) && hist) ? sraw[tid] : -CUDART_INF_F;
    __syncthreads();

    if (wid == 0) {
        float v[7];
        #pragma unroll
        for (int j = 0; j < 7; j++) v[j] = msc[lane + 32 * j];

        float kval[8]; int kidx[8];
        #pragma unroll
        for (int k = 0; k < Kk; k++) {
            float bv_ = -CUDART_INF_F; int bi = 0x7fffffff;
            #pragma unroll
            for (int j = 0; j < 7; j++) {
                int ix = lane + 32 * j;
                if (v[j] > bv_ || (v[j] == bv_ && ix < bi)) { bv_ = v[j]; bi = ix; }
            }
            float wv_ = bv_; int wi = bi;
            #pragma unroll
            for (int o = 16; o; o >>= 1) {
                float ov = __shfl_xor_sync(0xffffffffu, wv_, o);
                int   oi = __shfl_xor_sync(0xffffffffu, wi, o);
                if (ov > wv_ || (ov == wv_ && oi < wi)) { wv_ = ov; wi = oi; }
            }
            kval[k] = wv_; kidx[k] = wi;
            #pragma unroll
            for (int j = 0; j < 7; j++)
                if (wi == lane + 32 * j) v[j] = -CUDART_INF_F;
        }

        const float kmax = kval[0];
        float p[8]; float sum = 0.f;
        #pragma unroll
        for (int k = 0; k < Kk; k++) {
            bool val = kval[k] > -1e30f;
            p[k] = val ? __expf(kval[k] - kmax) : 0.f;
            sum += p[k];
        }
        const float inv = 1.f / fmaxf(sum, 1.1920929e-07f);

        float myv = kval[0], myp = p[0]; int myi = kidx[0];
        #pragma unroll
        for (int k = 1; k < Kk; k++)
            if (lane == k) { myv = kval[k]; myp = p[k]; myi = kidx[k]; }

        if (lane < Kk) {
            bool val = myv > -1e30f;
            float w = val ? myp * inv : 0.f;
            g_selidx[b * Kk + lane] = val ? myi : -1;
            g_selw[b * Kk + lane]   = w;
            out[(size_t)Bb * Hh + (size_t)Bb * Tt + (size_t)b * Kk + lane] =
                val ? (float)myi : -1.f;
            if (val) out[(size_t)Bb * Hh + (size_t)b * Tt + myi] = w;
        }
    }
}

// ---------------------------------------------------------------------------
// Kernel 4: sparse V projection. 4 batches/block; 64-thread group g handles
// batch b0+g (its 8 selected rows), thread owns 4 output cols (one LDG.128 of
// Wv per i). Row-paired f32x2 accumulators.
// ---------------------------------------------------------------------------
__global__ void __launch_bounds__(256) v_kernel(
    const float* __restrict__ ss, const float* __restrict__ Wv,
    const float* __restrict__ bv, float* __restrict__ out) {
    __shared__ float ssel[Gg][Hh][Kk];   // [g][i][r], 32 KB
    __shared__ int   sidx[Gg * Kk];
    __shared__ float swt[Gg * Kk];

    const int tid = threadIdx.x;
    const int b0  = blockIdx.x * Gg;
    const int g   = tid >> 6;            // 0..3, uniform per warp
    const int c0  = (tid & 63) * 4;      // 4 output columns

    if (tid < Gg * Kk) {
        sidx[tid] = g_selidx[b0 * Kk + tid];
        swt[tid]  = g_selw[b0 * Kk + tid];
    }
    __syncthreads();

    // gather: 32 rows x 256 cols
    #pragma unroll
    for (int r = 0; r < Gg * Kk; r++) {
        int t = sidx[r];
        int gb = r >> 3;
        float val = 0.f;
        if (t >= 0) val = ss[((size_t)(b0 + gb) * Tt + t) * Hh + tid];
        ssel[gb][tid][r & 7] = val;
    }
    __syncthreads();

    // acc[rp*4 + c] holds (row 2rp, row 2rp+1) for output column c0+c
    ull acc[16];
    #pragma unroll
    for (int q = 0; q < 16; q++) acc[q] = pk2(0.f, 0.f);

    #pragma unroll 2
    for (int i = 0; i < Hh; i++) {
        float4 w = *(const float4*)(Wv + (size_t)i * Hh + c0);
        ull wd0 = pk2(w.x, w.x), wd1 = pk2(w.y, w.y);
        ull wd2 = pk2(w.z, w.z), wd3 = pk2(w.w, w.w);
        ulonglong2 A = *(const ulonglong2*)&ssel[g][i][0];  // rows 0..3
        ulonglong2 B = *(const ulonglong2*)&ssel[g][i][4];  // rows 4..7
        fma2(acc[0],  A.x, wd0); fma2(acc[1],  A.x, wd1);
        fma2(acc[2],  A.x, wd2); fma2(acc[3],  A.x, wd3);
        fma2(acc[4],  A.y, wd0); fma2(acc[5],  A.y, wd1);
        fma2(acc[6],  A.y, wd2); fma2(acc[7],  A.y, wd3);
        fma2(acc[8],  B.x, wd0); fma2(acc[9],  B.x, wd1);
        fma2(acc[10], B.x, wd2); fma2(acc[11], B.x, wd3);
        fma2(acc[12], B.y, wd0); fma2(acc[13], B.y, wd1);
        fma2(acc[14], B.y, wd2); fma2(acc[15], B.y, wd3);
    }

    float4 res;
    float* rp = (float*)&res;
    #pragma unroll
    for (int c = 0; c < 4; c++) {
        const float bvh = bv[c0 + c];
        float s = 0.f;
        #pragma unroll
        for (int q = 0; q < 4; q++) {
            float a0, a1;
            upk2(acc[q * 4 + c], a0, a1);
            s += swt[g * 8 + 2 * q]     * fmaxf(a0 + bvh, 0.f);
            s += swt[g * 8 + 2 * q + 1] * fmaxf(a1 + bvh, 0.f);
        }
        rp[c] = s;
    }
    *(float4*)(out + (size_t)(b0 + g) * Hh + c0) = res;
}

// ---------------------------------------------------------------------------
extern "C" void kernel_launch(void* const* d_in, const int* in_sizes, int n_in,
                              void* d_out, int out_size) {
    const float* cs = (const float*)d_in[0];
    const float* ss = (const float*)d_in[1];
    const unsigned int* mask = (const unsigned int*)d_in[2];
    const float* Wq = (const float*)d_in[3];
    const float* bq = (const float*)d_in[4];
    const float* Wk = (const float*)d_in[5];
    const float* bk = (const float*)d_in[6];
    const float* Wv = (const float*)d_in[7];
    const float* bv = (const float*)d_in[8];
    float* out = (float*)d_out;

    dim3 tb(32, 8);
    dim3 tg(8, 8);
    transpose_wk<<<tg, tb>>>(Wk);
    proj_kernel<<<Bb / 8, 256>>>(cs, Wq, bq, bk);
    score_kernel<<<Bb, 256>>>(ss, mask, out);
    v_kernel<<<Bb / Gg, 256>>>(ss, Wv, bv, out);
}

// round 4
// speedup vs baseline: 1.6148x; 1.0477x over previous
#include <cuda_runtime.h>
#include <math_constants.h>
#include <cstdint>

#define Bb 2048
#define Tt 200
#define Hh 256
#define Kk 8
#define GBv 8          // batches per v_kernel block

typedef unsigned long long ull;

// scratch (no allocs allowed)
__device__ float g_WkT[Hh * Hh];
__device__ float g_R[Bb * Hh];
__device__ float g_cb[Bb];
__device__ int   g_selidx[Bb * Kk];
__device__ float g_selw[Bb * Kk];

// ---- packed f32x2 helpers ----
__device__ __forceinline__ ull pk2(float x, float y) {
    ull r; asm("mov.b64 %0,{%1,%2};" : "=l"(r) : "f"(x), "f"(y)); return r;
}
__device__ __forceinline__ void upk2(ull v, float& x, float& y) {
    asm("mov.b64 {%0,%1},%2;" : "=f"(x), "=f"(y) : "l"(v));
}
__device__ __forceinline__ void fma2(ull& d, ull a, ull b) {
    asm("fma.rn.f32x2 %0,%1,%2,%0;" : "+l"(d) : "l"(a), "l"(b));
}
__device__ __forceinline__ unsigned tf32c(float f) {
    unsigned r; asm("cvt.rna.tf32.f32 %0, %1;" : "=r"(r) : "f"(f)); return r;
}
__device__ __forceinline__ void mma_tf32(float c[4], unsigned a0, unsigned a1,
                                         unsigned a2, unsigned a3,
                                         unsigned b0, unsigned b1) {
    asm volatile(
        "mma.sync.aligned.m16n8k8.row.col.f32.tf32.tf32.f32 "
        "{%0,%1,%2,%3},{%4,%5,%6,%7},{%8,%9},{%0,%1,%2,%3};"
        : "+f"(c[0]), "+f"(c[1]), "+f"(c[2]), "+f"(c[3])
        : "r"(a0), "r"(a1), "r"(a2), "r"(a3), "r"(b0), "r"(b1));
}

// ---------------------------------------------------------------------------
// Kernel 1: coalesced smem-tile transpose of Wk.
// ---------------------------------------------------------------------------
__global__ void __launch_bounds__(256) transpose_wk(const float* __restrict__ Wk) {
    __shared__ float tile[32][33];
    int x = blockIdx.x * 32 + threadIdx.x;
    int y = blockIdx.y * 32 + threadIdx.y;
    #pragma unroll
    for (int j = 0; j < 32; j += 8)
        tile[threadIdx.y + j][threadIdx.x] = Wk[(size_t)(y + j) * Hh + x];
    __syncthreads();
    int xo = blockIdx.y * 32 + threadIdx.x;
    int yo = blockIdx.x * 32 + threadIdx.y;
    #pragma unroll
    for (int j = 0; j < 32; j += 8)
        g_WkT[(size_t)(yo + j) * Hh + xo] = tile[threadIdx.x][threadIdx.y + j];
}

// ---------------------------------------------------------------------------
// Kernel 2: 8 batches/block (256 blocks): q = cs@Wq + bq, r = Wk@q, cb = bk.q
// ---------------------------------------------------------------------------
__global__ void __launch_bounds__(256) proj_kernel(
    const float* __restrict__ cs, const float* __restrict__ Wq,
    const float* __restrict__ bq, const float* __restrict__ bk) {
    __shared__ float cs_s[Hh][8];
    __shared__ float q_s[Hh][8];
    const int j  = threadIdx.x;
    const int b0 = blockIdx.x * 8;

    #pragma unroll
    for (int m = 0; m < 8; m++) cs_s[j][m] = cs[(size_t)(b0 + m) * Hh + j];
    __syncthreads();

    ull acc[4];
    const float bqj = bq[j];
    const ull binit = pk2(bqj, bqj);
    #pragma unroll
    for (int q = 0; q < 4; q++) acc[q] = binit;
    #pragma unroll 8
    for (int i = 0; i < Hh; i++) {
        float w = Wq[(size_t)i * Hh + j];
        ull ww = pk2(w, w);
        ulonglong2 A = *(const ulonglong2*)&cs_s[i][0];
        ulonglong2 B = *(const ulonglong2*)&cs_s[i][4];
        fma2(acc[0], A.x, ww); fma2(acc[1], A.y, ww);
        fma2(acc[2], B.x, ww); fma2(acc[3], B.y, ww);
    }
    #pragma unroll
    for (int q = 0; q < 4; q++) upk2(acc[q], q_s[j][2 * q], q_s[j][2 * q + 1]);
    __syncthreads();

    #pragma unroll
    for (int q = 0; q < 4; q++) acc[q] = pk2(0.f, 0.f);
    #pragma unroll 8
    for (int i = 0; i < Hh; i++) {
        float w = g_WkT[(size_t)i * Hh + j];
        ull ww = pk2(w, w);
        ulonglong2 A = *(const ulonglong2*)&q_s[i][0];
        ulonglong2 B = *(const ulonglong2*)&q_s[i][4];
        fma2(acc[0], A.x, ww); fma2(acc[1], A.y, ww);
        fma2(acc[2], B.x, ww); fma2(acc[3], B.y, ww);
    }
    #pragma unroll
    for (int q = 0; q < 4; q++) {
        float a, b;
        upk2(acc[q], a, b);
        g_R[(size_t)(b0 + 2 * q) * Hh + j]     = a;
        g_R[(size_t)(b0 + 2 * q + 1) * Hh + j] = b;
    }
    if (j < 8) {
        float s = 0.f;
        for (int i = 0; i < Hh; i++) s += bk[i] * q_s[i][j];
        g_cb[b0 + j] = s;
    }
}

// ---------------------------------------------------------------------------
// Kernel 3: scores (only t < lim matter!) -> top-8 -> attn/selected/scratch.
// ---------------------------------------------------------------------------
__global__ void __launch_bounds__(256) score_kernel(
    const float* __restrict__ ss, const unsigned int* __restrict__ mask,
    float* __restrict__ out) {
    __shared__ float r_s[Hh];
    __shared__ float sraw[Tt];
    __shared__ float msc[256];
    __shared__ int   redi[8];
    __shared__ int   i_bcast;

    const int tid  = threadIdx.x;
    const int lane = tid & 31;
    const int wid  = tid >> 5;
    const int b    = blockIdx.x;
    const float* ssb = ss + (size_t)b * Tt * Hh;

    r_s[tid] = g_R[(size_t)b * Hh + tid];
    const float cb = g_cb[b];

    int mt = 0;
    if (tid < Tt) mt = (mask[(size_t)b * Tt + tid] != 0u) ? 1 : 0;
    int sv = mt;
    #pragma unroll
    for (int o = 16; o; o >>= 1) sv += __shfl_xor_sync(0xffffffffu, sv, o);
    if (lane == 0) redi[wid] = sv;
    __syncthreads();
    if (wid == 0) {
        int v = (lane < 8) ? redi[lane] : 0;
        #pragma unroll
        for (int o = 4; o; o >>= 1) v += __shfl_xor_sync(0xffffffffu, v, o);
        if (lane == 0) i_bcast = v;
    }
    if (tid < Tt) out[(size_t)Bb * Hh + (size_t)b * Tt + tid] = 0.f;
    __syncthreads();
    const int lim = i_bcast - 1;          // rows t >= lim can never contribute
    const bool hist = (tid < Tt) && mt && (tid < lim);

    float rr[8];
    #pragma unroll
    for (int e = 0; e < 8; e++) rr[e] = r_s[lane * 8 + e];

    int t = wid;
    for (; t + 8 < lim; t += 16) {
        int t1 = t + 8;
        const float4* r0 = (const float4*)(ssb + (size_t)t  * Hh);
        const float4* r1 = (const float4*)(ssb + (size_t)t1 * Hh);
        float4 a0 = __ldcs(r0 + lane * 2), c0 = __ldcs(r0 + lane * 2 + 1);
        float4 a1 = __ldcs(r1 + lane * 2), c1 = __ldcs(r1 + lane * 2 + 1);
        float d0 = a0.x * rr[0] + a0.y * rr[1] + a0.z * rr[2] + a0.w * rr[3]
                 + c0.x * rr[4] + c0.y * rr[5] + c0.z * rr[6] + c0.w * rr[7];
        float d1 = a1.x * rr[0] + a1.y * rr[1] + a1.z * rr[2] + a1.w * rr[3]
                 + c1.x * rr[4] + c1.y * rr[5] + c1.z * rr[6] + c1.w * rr[7];
        d0 += __shfl_xor_sync(0xffffffffu, d0, 16);
        d1 += __shfl_xor_sync(0xffffffffu, d1, 16);
        float e = (lane < 16) ? d0 : d1;
        e += __shfl_xor_sync(0xffffffffu, e, 8);
        e += __shfl_xor_sync(0xffffffffu, e, 4);
        e += __shfl_xor_sync(0xffffffffu, e, 2);
        e += __shfl_xor_sync(0xffffffffu, e, 1);
        if (lane == 0)  sraw[t]  = (e + cb) * 0.0625f;
        if (lane == 16) sraw[t1] = (e + cb) * 0.0625f;
    }
    if (t < lim) {
        const float4* r0 = (const float4*)(ssb + (size_t)t * Hh);
        float4 a = __ldcs(r0 + lane * 2), c = __ldcs(r0 + lane * 2 + 1);
        float d = a.x * rr[0] + a.y * rr[1] + a.z * rr[2] + a.w * rr[3]
                + c.x * rr[4] + c.y * rr[5] + c.z * rr[6] + c.w * rr[7];
        #pragma unroll
        for (int o = 16; o; o >>= 1) d += __shfl_xor_sync(0xffffffffu, d, o);
        if (lane == 0) sraw[t] = (d + cb) * 0.0625f;
    }
    __syncthreads();
    msc[tid] = ((tid < Tt) && hist) ? sraw[tid] : -CUDART_INF_F;
    __syncthreads();

    if (wid == 0) {
        float v[7];
        #pragma unroll
        for (int j = 0; j < 7; j++) v[j] = msc[lane + 32 * j];

        float kval[8]; int kidx[8];
        #pragma unroll
        for (int k = 0; k < Kk; k++) {
            float bv_ = -CUDART_INF_F; int bi = 0x7fffffff;
            #pragma unroll
            for (int j = 0; j < 7; j++) {
                int ix = lane + 32 * j;
                if (v[j] > bv_ || (v[j] == bv_ && ix < bi)) { bv_ = v[j]; bi = ix; }
            }
            float wv_ = bv_; int wi = bi;
            #pragma unroll
            for (int o = 16; o; o >>= 1) {
                float ov = __shfl_xor_sync(0xffffffffu, wv_, o);
                int   oi = __shfl_xor_sync(0xffffffffu, wi, o);
                if (ov > wv_ || (ov == wv_ && oi < wi)) { wv_ = ov; wi = oi; }
            }
            kval[k] = wv_; kidx[k] = wi;
            #pragma unroll
            for (int j = 0; j < 7; j++)
                if (wi == lane + 32 * j) v[j] = -CUDART_INF_F;
        }

        const float kmax = kval[0];
        float p[8]; float sum = 0.f;
        #pragma unroll
        for (int k = 0; k < Kk; k++) {
            bool val = kval[k] > -1e30f;
            p[k] = val ? __expf(kval[k] - kmax) : 0.f;
            sum += p[k];
        }
        const float inv = 1.f / fmaxf(sum, 1.1920929e-07f);

        float myv = kval[0], myp = p[0]; int myi = kidx[0];
        #pragma unroll
        for (int k = 1; k < Kk; k++)
            if (lane == k) { myv = kval[k]; myp = p[k]; myi = kidx[k]; }

        if (lane < Kk) {
            bool val = myv > -1e30f;
            float w = val ? myp * inv : 0.f;
            g_selidx[b * Kk + lane] = val ? myi : -1;
            g_selw[b * Kk + lane]   = w;
            out[(size_t)Bb * Hh + (size_t)Bb * Tt + (size_t)b * Kk + lane] =
                val ? (float)myi : -1.f;
            if (val) out[(size_t)Bb * Hh + (size_t)b * Tt + myi] = w;
        }
    }
}

// ---------------------------------------------------------------------------
// Kernel 4: sparse V projection via tf32 mma.sync.
// Block: 8 batches -> A = 64 gathered rows x K=256, B = Wv (K=256 x N=256).
// 8 warps: wm = w&3 (m-tile of 16 rows), wn = w>>2 (128-col half).
// Epilogue: bias + relu + row-weight, xor-shuffle reduce 8 rows per batch.
// ---------------------------------------------------------------------------
#define AST 260          // A smem stride (floats) -> conflict-free A frags
#define BST 264          // B smem stride (floats) -> conflict-free B frags
#define VSMEM_BYTES ((64 * AST + 32 * BST + Hh + 64) * 4 + 64 * 4)

__global__ void __launch_bounds__(256, 2) v_kernel(
    const float* __restrict__ ss, const float* __restrict__ Wv,
    const float* __restrict__ bv, float* __restrict__ out) {
    extern __shared__ float smf[];
    float*    As   = smf;                       // 64 x AST (tf32 bits)
    float*    Bs   = As + 64 * AST;             // 32 x BST (tf32 bits)
    float*    bvs  = Bs + 32 * BST;             // 256
    float*    swts = bvs + Hh;                  // 64
    int*      sidx = (int*)(swts + 64);         // 64
    unsigned* AsU  = (unsigned*)As;
    unsigned* BsU  = (unsigned*)Bs;

    const int tid  = threadIdx.x;
    const int lane = tid & 31;
    const int w    = tid >> 5;
    const int wm   = w & 3;
    const int wn   = w >> 2;
    const int g    = lane >> 2;    // groupID
    const int tg   = lane & 3;     // threadID-in-group
    const int b0   = blockIdx.x * GBv;

    if (tid < 64) {
        sidx[tid] = g_selidx[b0 * Kk + tid];
        swts[tid] = g_selw[b0 * Kk + tid];
    }
    bvs[tid] = bv[tid];
    __syncthreads();

    // gather 64 rows of state_sequence -> As (tf32-converted), coalesced
    for (int r = 0; r < 64; r++) {
        int t = sidx[r];
        float val = 0.f;
        if (t >= 0)
            val = ss[((size_t)(b0 + (r >> 3)) * Tt + t) * Hh + tid];
        AsU[r * AST + tid] = tf32c(val);
    }

    float c[16][4];
    #pragma unroll
    for (int nt = 0; nt < 16; nt++)
        #pragma unroll
        for (int q = 0; q < 4; q++) c[nt][q] = 0.f;

    const int arow = 16 * wm + g;
    for (int kc = 0; kc < 8; kc++) {
        __syncthreads();
        // stage B chunk: Wv rows kc*32 .. +32, tf32-converted
        #pragma unroll
        for (int it = 0; it < 8; it++) {
            int li = it * 256 + tid;             // 0..2047
            int kr = li >> 6;                    // 0..31
            int c4 = li & 63;                    // float4 index in row
            float4 wv4 = __ldg((const float4*)(Wv + ((size_t)(kc * 32 + kr)) * Hh + c4 * 4));
            uint4 t4;
            t4.x = tf32c(wv4.x); t4.y = tf32c(wv4.y);
            t4.z = tf32c(wv4.z); t4.w = tf32c(wv4.w);
            *(uint4*)&BsU[kr * BST + c4 * 4] = t4;
        }
        __syncthreads();

        #pragma unroll
        for (int ks = 0; ks < 4; ks++) {
            int kabs = kc * 32 + ks * 8;
            unsigned a0 = AsU[arow * AST + kabs + tg];
            unsigned a1 = AsU[(arow + 8) * AST + kabs + tg];
            unsigned a2 = AsU[arow * AST + kabs + tg + 4];
            unsigned a3 = AsU[(arow + 8) * AST + kabs + tg + 4];
            #pragma unroll
            for (int nt = 0; nt < 16; nt++) {
                int n = wn * 128 + nt * 8 + g;
                unsigned bb0 = BsU[(ks * 8 + tg) * BST + n];
                unsigned bb1 = BsU[(ks * 8 + tg + 4) * BST + n];
                mma_tf32(c[nt], a0, a1, a2, a3, bb0, bb1);
            }
        }
    }

    // epilogue: rows 16wm+g (batch L0) and 16wm+g+8 (batch L0+1)
    const int L0 = 2 * wm;
    const float w0 = swts[L0 * 8 + g];
    const float w1 = swts[(L0 + 1) * 8 + g];
    #pragma unroll
    for (int nt = 0; nt < 16; nt++) {
        int cbase = wn * 128 + nt * 8 + 2 * tg;
        float bv0 = bvs[cbase], bv1 = bvs[cbase + 1];
        float v0 = w0 * fmaxf(c[nt][0] + bv0, 0.f);
        float v1 = w0 * fmaxf(c[nt][1] + bv1, 0.f);
        float v2 = w1 * fmaxf(c[nt][2] + bv0, 0.f);
        float v3 = w1 * fmaxf(c[nt][3] + bv1, 0.f);
        #pragma unroll
        for (int o = 4; o <= 16; o <<= 1) {
            v0 += __shfl_xor_sync(0xffffffffu, v0, o);
            v1 += __shfl_xor_sync(0xffffffffu, v1, o);
            v2 += __shfl_xor_sync(0xffffffffu, v2, o);
            v3 += __shfl_xor_sync(0xffffffffu, v3, o);
        }
        if (g == 0) {
            out[(size_t)(b0 + L0) * Hh + cbase]         = v0;
            out[(size_t)(b0 + L0) * Hh + cbase + 1]     = v1;
            out[(size_t)(b0 + L0 + 1) * Hh + cbase]     = v2;
            out[(size_t)(b0 + L0 + 1) * Hh + cbase + 1] = v3;
        }
    }
}

// ---------------------------------------------------------------------------
extern "C" void kernel_launch(void* const* d_in, const int* in_sizes, int n_in,
                              void* d_out, int out_size) {
    const float* cs = (const float*)d_in[0];
    const float* ss = (const float*)d_in[1];
    const unsigned int* mask = (const unsigned int*)d_in[2];
    const float* Wq = (const float*)d_in[3];
    const float* bq = (const float*)d_in[4];
    const float* Wk = (const float*)d_in[5];
    const float* bk = (const float*)d_in[6];
    const float* Wv = (const float*)d_in[7];
    const float* bv = (const float*)d_in[8];
    float* out = (float*)d_out;

    static bool attr_set = false;
    if (!attr_set) {
        cudaFuncSetAttribute(v_kernel, cudaFuncAttributeMaxDynamicSharedMemorySize,
                             VSMEM_BYTES);
        attr_set = true;
    }

    dim3 tb(32, 8);
    dim3 tg(8, 8);
    transpose_wk<<<tg, tb>>>(Wk);
    proj_kernel<<<Bb / 8, 256>>>(cs, Wq, bq, bk);
    score_kernel<<<Bb, 256>>>(ss, mask, out);
    v_kernel<<<Bb / GBv, 256, VSMEM_BYTES>>>(ss, Wv, bv, out);
}

// round 5
// speedup vs baseline: 2.4631x; 1.5253x over previous
#include <cuda_runtime.h>
#include <math_constants.h>
#include <cstdint>

#define Bb 2048
#define Tt 200
#define Hh 256
#define Kk 8
#define GBv 4          // batches per v_kernel block
#define AST 260        // A smem stride (floats): conflict-free a-frag reads

typedef unsigned long long ull;

// scratch (no allocs allowed)
__device__ float    g_WkT[Hh * Hh];
__device__ float    g_R[Bb * Hh];
__device__ float    g_cb[Bb];
__device__ int      g_selidx[Bb * Kk];
__device__ float    g_selw[Bb * Kk];
__device__ unsigned g_Bfrag[Hh * Hh];   // frag-packed tf32 Wv (256 KB)

// ---- packed f32x2 helpers ----
__device__ __forceinline__ ull pk2(float x, float y) {
    ull r; asm("mov.b64 %0,{%1,%2};" : "=l"(r) : "f"(x), "f"(y)); return r;
}
__device__ __forceinline__ void upk2(ull v, float& x, float& y) {
    asm("mov.b64 {%0,%1},%2;" : "=f"(x), "=f"(y) : "l"(v));
}
__device__ __forceinline__ void fma2(ull& d, ull a, ull b) {
    asm("fma.rn.f32x2 %0,%1,%2,%0;" : "+l"(d) : "l"(a), "l"(b));
}
__device__ __forceinline__ unsigned tf32c(float f) {
    unsigned r; asm("cvt.rna.tf32.f32 %0, %1;" : "=r"(r) : "f"(f)); return r;
}
__device__ __forceinline__ void mma_tf32(float c[4], unsigned a0, unsigned a1,
                                         unsigned a2, unsigned a3,
                                         unsigned b0, unsigned b1) {
    asm volatile(
        "mma.sync.aligned.m16n8k8.row.col.f32.tf32.tf32.f32 "
        "{%0,%1,%2,%3},{%4,%5,%6,%7},{%8,%9},{%0,%1,%2,%3};"
        : "+f"(c[0]), "+f"(c[1]), "+f"(c[2]), "+f"(c[3])
        : "r"(a0), "r"(a1), "r"(a2), "r"(a3), "r"(b0), "r"(b1));
}

// ---------------------------------------------------------------------------
// Kernel 1: coalesced smem-tile transpose of Wk.
// ---------------------------------------------------------------------------
__global__ void __launch_bounds__(256) transpose_wk(const float* __restrict__ Wk) {
    __shared__ float tile[32][33];
    int x = blockIdx.x * 32 + threadIdx.x;
    int y = blockIdx.y * 32 + threadIdx.y;
    #pragma unroll
    for (int j = 0; j < 32; j += 8)
        tile[threadIdx.y + j][threadIdx.x] = Wk[(size_t)(y + j) * Hh + x];
    __syncthreads();
    int xo = blockIdx.y * 32 + threadIdx.x;
    int yo = blockIdx.x * 32 + threadIdx.y;
    #pragma unroll
    for (int j = 0; j < 32; j += 8)
        g_WkT[(size_t)(yo + j) * Hh + xo] = tile[threadIdx.x][threadIdx.y + j];
}

// ---------------------------------------------------------------------------
// Kernel 1b: pack Wv into per-lane tf32 B-fragments for m16n8k8.row.col.
// Frag (kt, ntg, lane=4g+tg): b0 = Wv[kt*8+tg][ntg*8+g], b1 = Wv[kt*8+tg+4][..]
// ---------------------------------------------------------------------------
__global__ void __launch_bounds__(256) wv_prep(const float* __restrict__ Wv) {
    int idx  = blockIdx.x * 256 + threadIdx.x;   // 0 .. 32767
    int kt   = idx >> 10;
    int rem  = idx & 1023;
    int ntg  = rem >> 5;
    int lane = rem & 31;
    int g = lane >> 2, tg = lane & 3;
    int col = ntg * 8 + g;
    unsigned b0 = tf32c(Wv[(size_t)(kt * 8 + tg) * Hh + col]);
    unsigned b1 = tf32c(Wv[(size_t)(kt * 8 + tg + 4) * Hh + col]);
    uint2 v; v.x = b0; v.y = b1;
    *(uint2*)&g_Bfrag[idx * 2] = v;
}

// ---------------------------------------------------------------------------
// Kernel 2: 8 batches/block (256 blocks): q = cs@Wq + bq, r = Wk@q, cb = bk.q
// ---------------------------------------------------------------------------
__global__ void __launch_bounds__(256) proj_kernel(
    const float* __restrict__ cs, const float* __restrict__ Wq,
    const float* __restrict__ bq, const float* __restrict__ bk) {
    __shared__ float cs_s[Hh][8];
    __shared__ float q_s[Hh][8];
    const int j  = threadIdx.x;
    const int b0 = blockIdx.x * 8;

    #pragma unroll
    for (int m = 0; m < 8; m++) cs_s[j][m] = cs[(size_t)(b0 + m) * Hh + j];
    __syncthreads();

    ull acc[4];
    const float bqj = bq[j];
    const ull binit = pk2(bqj, bqj);
    #pragma unroll
    for (int q = 0; q < 4; q++) acc[q] = binit;
    #pragma unroll 8
    for (int i = 0; i < Hh; i++) {
        float w = Wq[(size_t)i * Hh + j];
        ull ww = pk2(w, w);
        ulonglong2 A = *(const ulonglong2*)&cs_s[i][0];
        ulonglong2 B = *(const ulonglong2*)&cs_s[i][4];
        fma2(acc[0], A.x, ww); fma2(acc[1], A.y, ww);
        fma2(acc[2], B.x, ww); fma2(acc[3], B.y, ww);
    }
    #pragma unroll
    for (int q = 0; q < 4; q++) upk2(acc[q], q_s[j][2 * q], q_s[j][2 * q + 1]);
    __syncthreads();

    #pragma unroll
    for (int q = 0; q < 4; q++) acc[q] = pk2(0.f, 0.f);
    #pragma unroll 8
    for (int i = 0; i < Hh; i++) {
        float w = g_WkT[(size_t)i * Hh + j];
        ull ww = pk2(w, w);
        ulonglong2 A = *(const ulonglong2*)&q_s[i][0];
        ulonglong2 B = *(const ulonglong2*)&q_s[i][4];
        fma2(acc[0], A.x, ww); fma2(acc[1], A.y, ww);
        fma2(acc[2], B.x, ww); fma2(acc[3], B.y, ww);
    }
    #pragma unroll
    for (int q = 0; q < 4; q++) {
        float a, b;
        upk2(acc[q], a, b);
        g_R[(size_t)(b0 + 2 * q) * Hh + j]     = a;
        g_R[(size_t)(b0 + 2 * q + 1) * Hh + j] = b;
    }
    if (j < 8) {
        float s = 0.f;
        for (int i = 0; i < Hh; i++) s += bk[i] * q_s[i][j];
        g_cb[b0 + j] = s;
    }
}

// ---------------------------------------------------------------------------
// Kernel 3: scores (rows t < lim only) -> top-8 -> attn/selected/scratch.
// 4 rows in flight per warp iteration for MLP.
// ---------------------------------------------------------------------------
__global__ void __launch_bounds__(256) score_kernel(
    const float* __restrict__ ss, const unsigned int* __restrict__ mask,
    float* __restrict__ out) {
    __shared__ float r_s[Hh];
    __shared__ float sraw[Tt];
    __shared__ float msc[256];
    __shared__ int   redi[8];
    __shared__ int   i_bcast;

    const int tid  = threadIdx.x;
    const int lane = tid & 31;
    const int wid  = tid >> 5;
    const int b    = blockIdx.x;
    const float* ssb = ss + (size_t)b * Tt * Hh;

    r_s[tid] = g_R[(size_t)b * Hh + tid];
    const float cb = g_cb[b];

    int mt = 0;
    if (tid < Tt) mt = (mask[(size_t)b * Tt + tid] != 0u) ? 1 : 0;
    int sv = mt;
    #pragma unroll
    for (int o = 16; o; o >>= 1) sv += __shfl_xor_sync(0xffffffffu, sv, o);
    if (lane == 0) redi[wid] = sv;
    __syncthreads();
    if (wid == 0) {
        int v = (lane < 8) ? redi[lane] : 0;
        #pragma unroll
        for (int o = 4; o; o >>= 1) v += __shfl_xor_sync(0xffffffffu, v, o);
        if (lane == 0) i_bcast = v;
    }
    if (tid < Tt) out[(size_t)Bb * Hh + (size_t)b * Tt + tid] = 0.f;
    __syncthreads();
    const int lim = i_bcast - 1;
    const bool hist = (tid < Tt) && mt && (tid < lim);

    float rr[8];
    #pragma unroll
    for (int e = 0; e < 8; e++) rr[e] = r_s[lane * 8 + e];

    int t = wid;
    for (; t + 24 < lim; t += 32) {
        float d[4];
        #pragma unroll
        for (int u = 0; u < 4; u++) {
            const float4* rw = (const float4*)(ssb + (size_t)(t + 8 * u) * Hh);
            float4 a = __ldcs(rw + lane * 2), c = __ldcs(rw + lane * 2 + 1);
            d[u] = a.x * rr[0] + a.y * rr[1] + a.z * rr[2] + a.w * rr[3]
                 + c.x * rr[4] + c.y * rr[5] + c.z * rr[6] + c.w * rr[7];
        }
        d[0] += __shfl_xor_sync(0xffffffffu, d[0], 16);
        d[1] += __shfl_xor_sync(0xffffffffu, d[1], 16);
        d[2] += __shfl_xor_sync(0xffffffffu, d[2], 16);
        d[3] += __shfl_xor_sync(0xffffffffu, d[3], 16);
        float e01 = (lane < 16) ? d[0] : d[1];
        float e23 = (lane < 16) ? d[2] : d[3];
        #pragma unroll
        for (int o = 8; o; o >>= 1) {
            e01 += __shfl_xor_sync(0xffffffffu, e01, o);
            e23 += __shfl_xor_sync(0xffffffffu, e23, o);
        }
        if (lane == 0)  { sraw[t]      = (e01 + cb) * 0.0625f;
                          sraw[t + 16] = (e23 + cb) * 0.0625f; }
        if (lane == 16) { sraw[t + 8]  = (e01 + cb) * 0.0625f;
                          sraw[t + 24] = (e23 + cb) * 0.0625f; }
    }
    for (; t < lim; t += 8) {
        const float4* rw = (const float4*)(ssb + (size_t)t * Hh);
        float4 a = __ldcs(rw + lane * 2), c = __ldcs(rw + lane * 2 + 1);
        float d = a.x * rr[0] + a.y * rr[1] + a.z * rr[2] + a.w * rr[3]
                + c.x * rr[4] + c.y * rr[5] + c.z * rr[6] + c.w * rr[7];
        #pragma unroll
        for (int o = 16; o; o >>= 1) d += __shfl_xor_sync(0xffffffffu, d, o);
        if (lane == 0) sraw[t] = (d + cb) * 0.0625f;
    }
    __syncthreads();
    msc[tid] = ((tid < Tt) && hist) ? sraw[tid] : -CUDART_INF_F;
    __syncthreads();

    if (wid == 0) {
        float v[7];
        #pragma unroll
        for (int j = 0; j < 7; j++) v[j] = msc[lane + 32 * j];

        float kval[8]; int kidx[8];
        #pragma unroll
        for (int k = 0; k < Kk; k++) {
            float bv_ = -CUDART_INF_F; int bi = 0x7fffffff;
            #pragma unroll
            for (int j = 0; j < 7; j++) {
                int ix = lane + 32 * j;
                if (v[j] > bv_ || (v[j] == bv_ && ix < bi)) { bv_ = v[j]; bi = ix; }
            }
            float wv_ = bv_; int wi = bi;
            #pragma unroll
            for (int o = 16; o; o >>= 1) {
                float ov = __shfl_xor_sync(0xffffffffu, wv_, o);
                int   oi = __shfl_xor_sync(0xffffffffu, wi, o);
                if (ov > wv_ || (ov == wv_ && oi < wi)) { wv_ = ov; wi = oi; }
            }
            kval[k] = wv_; kidx[k] = wi;
            #pragma unroll
            for (int j = 0; j < 7; j++)
                if (wi == lane + 32 * j) v[j] = -CUDART_INF_F;
        }

        const float kmax = kval[0];
        float p[8]; float sum = 0.f;
        #pragma unroll
        for (int k = 0; k < Kk; k++) {
            bool val = kval[k] > -1e30f;
            p[k] = val ? __expf(kval[k] - kmax) : 0.f;
            sum += p[k];
        }
        const float inv = 1.f / fmaxf(sum, 1.1920929e-07f);

        float myv = kval[0], myp = p[0]; int myi = kidx[0];
        #pragma unroll
        for (int k = 1; k < Kk; k++)
            if (lane == k) { myv = kval[k]; myp = p[k]; myi = kidx[k]; }

        if (lane < Kk) {
            bool val = myv > -1e30f;
            float w = val ? myp * inv : 0.f;
            g_selidx[b * Kk + lane] = val ? myi : -1;
            g_selw[b * Kk + lane]   = w;
            out[(size_t)Bb * Hh + (size_t)Bb * Tt + (size_t)b * Kk + lane] =
                val ? (float)myi : -1.f;
            if (val) out[(size_t)Bb * Hh + (size_t)b * Tt + myi] = w;
        }
    }
}

// ---------------------------------------------------------------------------
// Kernel 4: sparse V projection via tf32 mma with frag-packed Wv from global.
// Block: 4 batches -> A = 32 rows x K=256 in smem. 8 warps = 2(m) x 4(n).
// B frags: direct LDG.64 per (kt, nt) from g_Bfrag (L1-resident after warm).
// ---------------------------------------------------------------------------
__global__ void __launch_bounds__(256) v_kernel(
    const float* __restrict__ ss, const float* __restrict__ bv,
    float* __restrict__ out) {
    __shared__ unsigned AsU[32 * AST];
    __shared__ float swts[32];
    __shared__ int   sidx[32];
    __shared__ float bvs[Hh];

    const int tid  = threadIdx.x;
    const int lane = tid & 31;
    const int w    = tid >> 5;
    const int wm   = w & 1;        // m-tile 0..1
    const int wn   = w >> 1;       // n quarter 0..3
    const int g    = lane >> 2;
    const int tg   = lane & 3;
    const int b0   = blockIdx.x * GBv;

    if (tid < 32) {
        sidx[tid] = g_selidx[b0 * Kk + tid];
        swts[tid] = g_selw[b0 * Kk + tid];
    }
    bvs[tid] = bv[tid];
    __syncthreads();

    // gather 32 rows -> As (tf32), coalesced
    #pragma unroll 4
    for (int r = 0; r < 32; r++) {
        int t = sidx[r];
        float val = 0.f;
        if (t >= 0)
            val = ss[((size_t)(b0 + (r >> 3)) * Tt + t) * Hh + tid];
        AsU[r * AST + tid] = tf32c(val);
    }
    __syncthreads();

    float c[8][4];
    #pragma unroll
    for (int nt = 0; nt < 8; nt++)
        #pragma unroll
        for (int q = 0; q < 4; q++) c[nt][q] = 0.f;

    const int arow = 16 * wm + g;
    const uint2* bp = (const uint2*)g_Bfrag;
    #pragma unroll 2
    for (int kt = 0; kt < 32; kt++) {
        int kabs = kt * 8;
        unsigned a0 = AsU[arow * AST + kabs + tg];
        unsigned a1 = AsU[(arow + 8) * AST + kabs + tg];
        unsigned a2 = AsU[arow * AST + kabs + tg + 4];
        unsigned a3 = AsU[(arow + 8) * AST + kabs + tg + 4];
        const uint2* bq_ = bp + ((size_t)kt * 32 + wn * 8) * 32 + lane;
        #pragma unroll
        for (int nt = 0; nt < 8; nt++) {
            uint2 bb = __ldg(bq_ + nt * 32);
            mma_tf32(c[nt], a0, a1, a2, a3, bb.x, bb.y);
        }
    }

    // epilogue: rows arow (batch 2wm) and arow+8 (batch 2wm+1)
    const int L0 = 2 * wm;
    const float w0 = swts[L0 * 8 + g];
    const float w1 = swts[(L0 + 1) * 8 + g];
    #pragma unroll
    for (int nt = 0; nt < 8; nt++) {
        int cbase = wn * 64 + nt * 8 + 2 * tg;
        float bv0 = bvs[cbase], bv1 = bvs[cbase + 1];
        float v0 = w0 * fmaxf(c[nt][0] + bv0, 0.f);
        float v1 = w0 * fmaxf(c[nt][1] + bv1, 0.f);
        float v2 = w1 * fmaxf(c[nt][2] + bv0, 0.f);
        float v3 = w1 * fmaxf(c[nt][3] + bv1, 0.f);
        #pragma unroll
        for (int o = 4; o <= 16; o <<= 1) {
            v0 += __shfl_xor_sync(0xffffffffu, v0, o);
            v1 += __shfl_xor_sync(0xffffffffu, v1, o);
            v2 += __shfl_xor_sync(0xffffffffu, v2, o);
            v3 += __shfl_xor_sync(0xffffffffu, v3, o);
        }
        if (g == 0) {
            out[(size_t)(b0 + L0) * Hh + cbase]         = v0;
            out[(size_t)(b0 + L0) * Hh + cbase + 1]     = v1;
            out[(size_t)(b0 + L0 + 1) * Hh + cbase]     = v2;
            out[(size_t)(b0 + L0 + 1) * Hh + cbase + 1] = v3;
        }
    }
}

// ---------------------------------------------------------------------------
extern "C" void kernel_launch(void* const* d_in, const int* in_sizes, int n_in,
                              void* d_out, int out_size) {
    const float* cs = (const float*)d_in[0];
    const float* ss = (const float*)d_in[1];
    const unsigned int* mask = (const unsigned int*)d_in[2];
    const float* Wq = (const float*)d_in[3];
    const float* bq = (const float*)d_in[4];
    const float* Wk = (const float*)d_in[5];
    const float* bk = (const float*)d_in[6];
    const float* Wv = (const float*)d_in[7];
    const float* bv = (const float*)d_in[8];
    float* out = (float*)d_out;

    dim3 tb(32, 8);
    dim3 tg(8, 8);
    transpose_wk<<<tg, tb>>>(Wk);
    wv_prep<<<128, 256>>>(Wv);
    proj_kernel<<<Bb / 8, 256>>>(cs, Wq, bq, bk);
    score_kernel<<<Bb, 256>>>(ss, mask, out);
    v_kernel<<<Bb / GBv, 256>>>(ss, bv, out);
}